// round 1
// baseline (speedup 1.0000x reference)
#include <cuda_runtime.h>

// CBOW HS loss:
// loss = -( sum_n logsig( dot(sum_c U[pos_u[n,c]], W[pos_w[n]]) )
//         + sum_n logsig(-dot(sum_c U[neg_u[n,c]], W[neg_w[n]]) ) )
//
// EMBED = 128 floats  -> 32 lanes x float4 per row (one warp per sample)
// C = 10 context rows

#define CW 10
#define E4 32   // 128 / 4

__device__ double g_acc;

__global__ void init_kernel() { g_acc = 0.0; }

__global__ void __launch_bounds__(256) cbow_kernel(
    const float4* __restrict__ u_emb,
    const float4* __restrict__ w_emb,
    const int*    __restrict__ pos_u,
    const int*    __restrict__ pos_w,
    const int*    __restrict__ neg_u,
    const int*    __restrict__ neg_w,
    int n_samples)
{
    const int warp = (blockIdx.x * blockDim.x + threadIdx.x) >> 5;
    const int lane = threadIdx.x & 31;

    float loss = 0.0f;

    if (warp < n_samples) {
        #pragma unroll
        for (int pass = 0; pass < 2; pass++) {
            const int* cu = pass ? neg_u : pos_u;
            const int* cw = pass ? neg_w : pos_w;

            // gather + sum-pool 10 context rows; front-batch loads for MLP
            float4 r[CW];
            #pragma unroll
            for (int i = 0; i < CW; i++) {
                int idx = __ldg(&cu[(size_t)warp * CW + i]);
                r[i] = __ldg(&u_emb[(size_t)idx * E4 + lane]);
            }
            float4 acc = r[0];
            #pragma unroll
            for (int i = 1; i < CW; i++) {
                acc.x += r[i].x; acc.y += r[i].y;
                acc.z += r[i].z; acc.w += r[i].w;
            }

            int t = __ldg(&cw[warp]);
            float4 tv = __ldg(&w_emb[(size_t)t * E4 + lane]);

            float p = acc.x * tv.x + acc.y * tv.y + acc.z * tv.z + acc.w * tv.w;
            #pragma unroll
            for (int o = 16; o > 0; o >>= 1)
                p += __shfl_xor_sync(0xffffffffu, p, o);

            float x = pass ? -p : p;
            // log_sigmoid(x) = min(x,0) - log1p(exp(-|x|))
            float ls = fminf(x, 0.0f) - log1pf(__expf(-fabsf(x)));
            loss += -ls;   // negative log-likelihood contribution
        }
    }

    // block reduce (all lanes hold the same value after shfl_xor butterfly)
    __shared__ float s_part[8];
    const int wid = threadIdx.x >> 5;
    if (lane == 0) s_part[wid] = loss;
    __syncthreads();
    if (threadIdx.x == 0) {
        float b = 0.0f;
        const int nwarps = blockDim.x >> 5;
        #pragma unroll
        for (int i = 0; i < 8; i++)
            if (i < nwarps) b += s_part[i];
        atomicAdd(&g_acc, (double)b);
    }
}

__global__ void finalize_kernel(float* out) { out[0] = (float)g_acc; }

extern "C" void kernel_launch(void* const* d_in, const int* in_sizes, int n_in,
                              void* d_out, int out_size)
{
    const float4* u_emb = (const float4*)d_in[0];
    const float4* w_emb = (const float4*)d_in[1];
    const int*    pos_u = (const int*)d_in[2];
    const int*    pos_w = (const int*)d_in[3];
    const int*    neg_u = (const int*)d_in[4];
    const int*    neg_w = (const int*)d_in[5];

    const int n_samples = in_sizes[3];   // pos_w has N elements

    init_kernel<<<1, 1>>>();

    const int threads = 256;                       // 8 warps/block
    const int warps_per_block = threads / 32;
    const int blocks = (n_samples + warps_per_block - 1) / warps_per_block;
    cbow_kernel<<<blocks, threads>>>(u_emb, w_emb, pos_u, pos_w, neg_u, neg_w,
                                     n_samples);

    finalize_kernel<<<1, 1>>>((float*)d_out);
}